// round 11
// baseline (speedup 1.0000x reference)
#include <cuda_runtime.h>

// 3x3 median blur, zero padding, fp32 NCHW (8,3,512,512).
// Vertical-streaming kernel: each thread owns a 16-row x 4-col strip and
// walks it as 8 two-row tiles. Adjacent tiles share 2 of 4 input rows
// (kept in a mod-4 rotating register buffer), so each tile loads only 2 new
// rows (6 LDG), issued right after the old rows die -> the remaining ~200cyc
// of merge alu work hides the load latency (software pipelining).
// Per tile: pair-sort 12 + 2x18 triples + 2x40 shared-pair merge = 128 alu
// ops / 8 px = 16/px, 0.84 LDG/px.

__device__ __forceinline__ float med3(float a, float b, float c) {
    return fmaxf(fminf(a, b), fminf(fmaxf(a, b), c));
}

// Merge 6 sorted column triples into 4 medians; shared pairs across pixels.
__device__ __forceinline__ void merge_row(const float lo[6], const float mi[6],
                                          const float hi[6], float* dst) {
    const float m12 = fmaxf(lo[1], lo[2]);
    const float m34 = fmaxf(lo[3], lo[4]);
    const float A0 = fmaxf(lo[0], m12);
    const float A1 = fmaxf(m12, lo[3]);
    const float A2 = fmaxf(lo[2], m34);
    const float A3 = fmaxf(m34, lo[5]);
    const float n12 = fminf(hi[1], hi[2]);
    const float n34 = fminf(hi[3], hi[4]);
    const float C0 = fminf(hi[0], n12);
    const float C1 = fminf(n12, hi[3]);
    const float C2 = fminf(hi[2], n34);
    const float C3 = fminf(n34, hi[5]);
    const float p12 = fminf(mi[1], mi[2]), q12 = fmaxf(mi[1], mi[2]);
    const float p34 = fminf(mi[3], mi[4]), q34 = fmaxf(mi[3], mi[4]);
    const float B0 = fmaxf(p12, fminf(mi[0], q12));
    const float B1 = fmaxf(p12, fminf(mi[3], q12));
    const float B2 = fmaxf(p34, fminf(mi[2], q34));
    const float B3 = fmaxf(p34, fminf(mi[5], q34));
    float4 o;
    o.x = med3(A0, B0, C0);
    o.y = med3(A1, B1, C1);
    o.z = med3(A2, B2, C2);
    o.w = med3(A3, B3, C3);
    *reinterpret_cast<float4*>(dst) = o;
}

template <bool CHECK>
__device__ __forceinline__ void load_row(float dst[6], const float* __restrict__ p,
                                         int yy, int x0, bool lx, bool rx) {
    if (CHECK && (unsigned)yy >= 512u) {
        #pragma unroll
        for (int j = 0; j < 6; ++j) dst[j] = 0.0f;
    } else {
        const float* __restrict__ row = p + yy * 512;
        const float4 a = *reinterpret_cast<const float4*>(row + x0);
        dst[1] = a.x; dst[2] = a.y; dst[3] = a.z; dst[4] = a.w;
        dst[0] = lx ? row[x0 - 1] : 0.0f;
        dst[5] = rx ? row[x0 + 4] : 0.0f;
    }
}

template <bool CHECK>
__device__ __forceinline__ void run_strip(const float* __restrict__ p,
                                          float* __restrict__ outp,
                                          int x0, int yTop) {
    const bool lx = (x0 > 0);
    const bool rx = (x0 + 4 < 512);

    // Rotating buffer: rows yTop-1 .. yTop+2 of the 6-wide column window.
    float r[4][6];
    load_row<CHECK>(r[0], p, yTop - 1, x0, lx, rx);
    load_row<CHECK>(r[1], p, yTop + 0, x0, lx, rx);
    load_row<CHECK>(r[2], p, yTop + 1, x0, lx, rx);
    load_row<CHECK>(r[3], p, yTop + 2, x0, lx, rx);

    float* dst = outp + yTop * 512 + x0;

    float mn[6], mx[6], lo[6], mi[6], hi[6];

    #pragma unroll
    for (int it = 0; it < 8; ++it) {
        const int ia = (2 * it) & 3;       // row y-1   (dies after triples A)
        const int ib = (2 * it + 1) & 3;   // row y     (dies after pair)
        const int ic = (2 * it + 2) & 3;   // row y+1   (kept for next tile)
        const int id = (2 * it + 3) & 3;   // row y+2   (kept for next tile)

        // Middle-pair sort (rows y, y+1) shared by both output windows.
        #pragma unroll
        for (int j = 0; j < 6; ++j) {
            mn[j] = fminf(r[ib][j], r[ic][j]);
            mx[j] = fmaxf(r[ib][j], r[ic][j]);
        }
        // Window A (rows y-1..y+1): insert row a. r[ia] dead afterwards.
        #pragma unroll
        for (int j = 0; j < 6; ++j) {
            const float a = r[ia][j];
            const float u = fmaxf(a, mn[j]);
            lo[j] = fminf(a, mn[j]);
            mi[j] = fminf(u, mx[j]);
            hi[j] = fmaxf(u, mx[j]);
        }
        // Prefetch next tile's two rows into the freed slots; the remaining
        // merge/triple alu work (~200+ cyc) hides the load latency.
        if (it < 7) {
            load_row<CHECK>(r[ia], p, yTop + 3 + 2 * it, x0, lx, rx);
            load_row<CHECK>(r[ib], p, yTop + 4 + 2 * it, x0, lx, rx);
        }
        merge_row(lo, mi, hi, dst);

        // Window B (rows y..y+2): insert row d into the retained pair.
        #pragma unroll
        for (int j = 0; j < 6; ++j) {
            const float d = r[id][j];
            const float w = fmaxf(d, mn[j]);
            lo[j] = fminf(d, mn[j]);
            mi[j] = fminf(w, mx[j]);
            hi[j] = fmaxf(w, mx[j]);
        }
        merge_row(lo, mi, hi, dst + 512);

        dst += 1024;
    }
}

__global__ __launch_bounds__(128, 6)
void MedianBlur_34505767256654_kernel(const float* __restrict__ in,
                                      float* __restrict__ out) {
    const int x0 = (blockIdx.x * 32 + threadIdx.x) * 4;       // 4 cols
    const int strip = blockIdx.y * 4 + threadIdx.y;           // 0..31
    const int yTop = strip * 16;                              // 16 rows/strip
    const int base = blockIdx.z * (512 * 512);                // 24 planes

    const float* __restrict__ p = in + base;
    float* __restrict__ o = out + base;

    // Only the first and last strips touch the vertical border.
    if (strip != 0 && strip != 31) {
        run_strip<false>(p, o, x0, yTop);
    } else {
        run_strip<true>(p, o, x0, yTop);
    }
}

extern "C" void kernel_launch(void* const* d_in, const int* in_sizes, int n_in,
                              void* d_out, int out_size) {
    (void)in_sizes; (void)n_in; (void)out_size;
    const float* x = (const float*)d_in[0];
    float* out = (float*)d_out;

    dim3 block(32, 4, 1);                 // 128 threads: 128 cols x 4 strips
    dim3 grid(512 / 128, 32 / 4, 24);     // (4, 8, 24) = 768 blocks
    MedianBlur_34505767256654_kernel<<<grid, block>>>(x, out);
}